// round 13
// baseline (speedup 1.0000x reference)
#include <cuda_runtime.h>

#define HDIM 2048
#define NT 512
#define MAXS 1000

typedef unsigned long long ull;

// ---------------- packed f32x2 helpers ----------------
__device__ __forceinline__ ull pk2(float lo, float hi) {
    ull r; asm("mov.b64 %0, {%1,%2};" : "=l"(r) : "f"(lo), "f"(hi)); return r;
}
__device__ __forceinline__ void upk2(ull v, float& lo, float& hi) {
    asm("mov.b64 {%0,%1}, %2;" : "=f"(lo), "=f"(hi) : "l"(v));
}
__device__ __forceinline__ ull fma2_(ull a, ull b, ull c) {
    ull d; asm("fma.rn.f32x2 %0, %1, %2, %3;" : "=l"(d) : "l"(a), "l"(b), "l"(c)); return d;
}
__device__ __forceinline__ float tanha(float x) {
    float y; asm("tanh.approx.f32 %0, %1;" : "=f"(y) : "f"(x)); return y;
}

// ---------------- threefry2x32 (JAX), key = (0, 42) ----------------
__device__ __forceinline__ void threefry2x32(unsigned k1, unsigned k2,
                                             unsigned x0, unsigned x1,
                                             unsigned* o0, unsigned* o1) {
    unsigned ks0 = k1, ks1 = k2, ks2 = k1 ^ k2 ^ 0x1BD11BDAu;
    x0 += ks0; x1 += ks1;
#define TF_R(r) { x0 += x1; x1 = (x1 << (r)) | (x1 >> (32 - (r))); x1 ^= x0; }
    TF_R(13) TF_R(15) TF_R(26) TF_R(6)   x0 += ks1; x1 += ks2 + 1u;
    TF_R(17) TF_R(29) TF_R(16) TF_R(24)  x0 += ks2; x1 += ks0 + 2u;
    TF_R(13) TF_R(15) TF_R(26) TF_R(6)   x0 += ks0; x1 += ks1 + 3u;
    TF_R(17) TF_R(29) TF_R(16) TF_R(24)  x0 += ks1; x1 += ks2 + 4u;
    TF_R(13) TF_R(15) TF_R(26) TF_R(6)   x0 += ks2; x1 += ks0 + 5u;
#undef TF_R
    *o0 = x0; *o1 = x1;
}

// XLA ErfInv32 (Giles) polynomial — matches lax.erf_inv on f32.
__device__ __forceinline__ float erfinv_xla(float x) {
    float w = -logf((1.0f - x) * (1.0f + x));
    float p;
    if (w < 5.0f) {
        w -= 2.5f;
        p = 2.81022636e-08f;
        p = fmaf(p, w, 3.43273939e-07f);
        p = fmaf(p, w, -3.5233877e-06f);
        p = fmaf(p, w, -4.39150654e-06f);
        p = fmaf(p, w, 0.00021858087f);
        p = fmaf(p, w, -0.00125372503f);
        p = fmaf(p, w, -0.00417768164f);
        p = fmaf(p, w, 0.246640727f);
        p = fmaf(p, w, 1.50140941f);
    } else {
        w = sqrtf(w) - 3.0f;
        p = -0.000200214257f;
        p = fmaf(p, w, 0.000100950558f);
        p = fmaf(p, w, 0.00134934322f);
        p = fmaf(p, w, -0.00367342844f);
        p = fmaf(p, w, 0.00573950773f);
        p = fmaf(p, w, -0.0076224613f);
        p = fmaf(p, w, 0.00943887047f);
        p = fmaf(p, w, 1.00167406f);
        p = fmaf(p, w, 2.83297682f);
    }
    return p * x;
}

__device__ __forceinline__ float bits_to_normal(unsigned bits) {
    const float lo = -0.99999994f;            // nextafterf(-1, 0)
    const float span = 1.0f - lo;
    float f = __uint_as_float((bits >> 9) | 0x3f800000u) - 1.0f;  // [0,1)
    float u = fmaxf(lo, f * span + lo);
    return 1.41421356f * erfinv_xla(u);
}

__global__ void __launch_bounds__(NT, 1)
sketch_decoder_kernel(const float* __restrict__ W_ih,
                      const float* __restrict__ b_ih,
                      const float* __restrict__ b_hh,
                      const float* __restrict__ W_lin,
                      const float* __restrict__ b_lin,
                      const int*   __restrict__ msp,
                      float* __restrict__ out) {
    __shared__ float  s_acc[7][NT];      // partial sums, row-contiguous (float4 reduce)
    __shared__ float  s_red[8];          // 7 nonlinearized outputs (+pad), float4-aligned
    __shared__ float2 s_eps[MAXS];

    const int tid = threadIdx.x;
    const int warp = tid >> 5, lane = tid & 31;
    int ms = msp[0];
    if (ms < 0) ms = 0;
    if (ms > MAXS) ms = MAXS;

    // ---- init output buffer: row0 = [0,0,1,0,0], rest = [0,0,0,0,1] ----
    for (int idx = tid; idx < ms * 5; idx += NT) {
        int r = idx / 5, c = idx - r * 5;
        out[idx] = (r == 0) ? ((c == 2) ? 1.0f : 0.0f)
                            : ((c == 4) ? 1.0f : 0.0f);
    }

    // ---- precompute eps (JAX partitionable threefry, key(42)) ----
    for (int i = tid; i < ms; i += NT) {
        unsigned r0, r1;
        threefry2x32(0u, 42u, 0u, (unsigned)(2 * i), &r0, &r1);
        float ex = bits_to_normal(r0 ^ r1);
        threefry2x32(0u, 42u, 0u, (unsigned)(2 * i + 1), &r0, &r1);
        float ey = bits_to_normal(r0 ^ r1);
        s_eps[i] = make_float2(ex, ey);
    }
    if (tid == 0) s_red[7] = 0.0f;

    // per-thread bias for the reduce warps (lane 0 of warps 0-6 only)
    const float myblin = (warp < 7 && lane == 0) ? b_lin[warp] : 0.0f;

    // ---- register-resident packed weights (4 elements / thread = 2 pairs) ----
    // i,o gate rows pre-scaled by 0.5 (sigmoid via 0.5*tanh(0.5x)+0.5).
    // sum-1 fold: gate = w0*l0 + w1*l1 + (w2-w4)*sm0 + (w3-w4)*sm1 + (b + w4).
    ull wi[2][4], wg[2][4], wo[2][4], wl[2][7], bi[2], bg[2], bo[2];
    #pragma unroll
    for (int q = 0; q < 2; q++) {
        const int e0 = tid + (2 * q) * NT;
        const int e1 = e0 + NT;
        const int g0 = 2 * HDIM + e0, g1 = 2 * HDIM + e1;
        const int o0 = 3 * HDIM + e0, o1 = 3 * HDIM + e1;
        #pragma unroll
        for (int c = 0; c < 2; c++) {   // l0, l1 coefficients
            wi[q][c] = pk2(0.5f * W_ih[e0 * 5 + c], 0.5f * W_ih[e1 * 5 + c]);
            wg[q][c] = pk2(W_ih[g0 * 5 + c],        W_ih[g1 * 5 + c]);
            wo[q][c] = pk2(0.5f * W_ih[o0 * 5 + c], 0.5f * W_ih[o1 * 5 + c]);
        }
        #pragma unroll
        for (int c = 2; c < 4; c++) {   // folded sm0, sm1 coefficients
            wi[q][c] = pk2(0.5f * (W_ih[e0 * 5 + c] - W_ih[e0 * 5 + 4]),
                           0.5f * (W_ih[e1 * 5 + c] - W_ih[e1 * 5 + 4]));
            wg[q][c] = pk2(W_ih[g0 * 5 + c] - W_ih[g0 * 5 + 4],
                           W_ih[g1 * 5 + c] - W_ih[g1 * 5 + 4]);
            wo[q][c] = pk2(0.5f * (W_ih[o0 * 5 + c] - W_ih[o0 * 5 + 4]),
                           0.5f * (W_ih[o1 * 5 + c] - W_ih[o1 * 5 + 4]));
        }
        bi[q] = pk2(0.5f * (b_ih[e0] + b_hh[e0] + W_ih[e0 * 5 + 4]),
                    0.5f * (b_ih[e1] + b_hh[e1] + W_ih[e1 * 5 + 4]));
        bg[q] = pk2(b_ih[g0] + b_hh[g0] + W_ih[g0 * 5 + 4],
                    b_ih[g1] + b_hh[g1] + W_ih[g1 * 5 + 4]);
        bo[q] = pk2(0.5f * (b_ih[o0] + b_hh[o0] + W_ih[o0 * 5 + 4]),
                    0.5f * (b_ih[o1] + b_hh[o1] + W_ih[o1 * 5 + 4]));
        #pragma unroll
        for (int k = 0; k < 7; k++)
            wl[q][k] = pk2(W_lin[k * HDIM + e0], W_lin[k * HDIM + e1]);
    }

    const float L2E = 1.442695041f;

    // `last` lives in registers (redundant per-thread copy; identical IEEE
    // ops from identical s_red values -> identical across threads).
    float lx = 0.0f, ly = 0.0f, lm0 = 1.0f, lm1 = 0.0f;  // init row [0,0,1,0,0]

    __syncthreads();

    // step 0 of the reference is a provable no-op (write gated by i>0) -> start at 1
    for (int i = 1; i < ms; i++) {
        ull lp[4];
        lp[0] = pk2(lx, lx); lp[1] = pk2(ly, ly);
        lp[2] = pk2(lm0, lm0); lp[3] = pk2(lm1, lm1);

        ull acc[7];
        #pragma unroll
        for (int k = 0; k < 7; k++) acc[k] = 0ull;

        #pragma unroll
        for (int q = 0; q < 2; q++) {
            ull gi = bi[q], gg = bg[q], go = bo[q];
            #pragma unroll
            for (int c = 0; c < 4; c++) {
                gi = fma2_(wi[q][c], lp[c], gi);
                gg = fma2_(wg[q][c], lp[c], gg);
                go = fma2_(wo[q][c], lp[c], go);
            }
            float i0, i1, g0, g1, o0, o1;
            upk2(gi, i0, i1); upk2(gg, g0, g1); upk2(go, o0, o1);
            // sigmoid(x) = 0.5*tanh(0.5x)+0.5 ; 0.5 pre-folded into gi/go
            float si0 = fmaf(tanha(i0), 0.5f, 0.5f);
            float si1 = fmaf(tanha(i1), 0.5f, 0.5f);
            float so0 = fmaf(tanha(o0), 0.5f, 0.5f);
            float so1 = fmaf(tanha(o1), 0.5f, 0.5f);
            float c0 = si0 * tanha(g0);
            float c1 = si1 * tanha(g1);
            float tc0, tc1;
            if (q < 1) {
                // Taylor-9 tanh on FMA pipe (|c| small; validated R4/R8 at ~3e-7)
                float t0 = c0 * c0, t1 = c1 * c1;
                float p0 = fmaf(0.02186949f, t0, -0.05396825f);
                float p1 = fmaf(0.02186949f, t1, -0.05396825f);
                p0 = fmaf(p0, t0, 0.13333334f);
                p1 = fmaf(p1, t1, 0.13333334f);
                p0 = fmaf(p0, t0, -0.33333334f);
                p1 = fmaf(p1, t1, -0.33333334f);
                p0 = fmaf(p0, t0, 1.0f);
                p1 = fmaf(p1, t1, 1.0f);
                tc0 = p0 * c0; tc1 = p1 * c1;
            } else {
                // MUFU path (pipe balancing: both pipes ~equal busy)
                tc0 = tanha(c0); tc1 = tanha(c1);
            }
            float h0 = so0 * tc0;
            float h1 = so1 * tc1;
            ull hp = pk2(h0, h1);
            #pragma unroll
            for (int k = 0; k < 7; k++)
                acc[k] = fma2_(wl[q][k], hp, acc[k]);
        }

        #pragma unroll
        for (int k = 0; k < 7; k++) {
            float a0, a1; upk2(acc[k], a0, a1);
            s_acc[k][tid] = a0 + a1;
        }
        __syncthreads();   // bar1: s_acc complete

        // warps 0-6: reduce output k=warp over 512 partials, then nonlinearity:
        //   k=0,2 : tanh(o_k)            (raw, for sx/sy)
        //   k=1,3 : exp(0.5*tanh(o_k))   (sig_x / sig_y)
        //   k=4..6: exp(tanh(o_k))       (unnormalized softmax; arg in [-1,1])
        if (warp < 7) {
            const float4* row = (const float4*)s_acc[warp];
            float4 v0 = row[lane];
            float4 v1 = row[lane + 32];
            float4 v2 = row[lane + 64];
            float4 v3 = row[lane + 96];
            float va = ((v0.x + v0.y) + (v0.z + v0.w))
                     + ((v1.x + v1.y) + (v1.z + v1.w));
            float vb = ((v2.x + v2.y) + (v2.z + v2.w))
                     + ((v3.x + v3.y) + (v3.z + v3.w));
            float v = va + vb;
            // 3 xor rounds -> lane0 holds sum over lanes == 0 (mod 4)
            v += __shfl_xor_sync(0xffffffffu, v, 16);
            v += __shfl_xor_sync(0xffffffffu, v, 8);
            v += __shfl_xor_sync(0xffffffffu, v, 4);
            // parallel gather of the 3 remaining mod-4 classes
            float g1 = __shfl_sync(0xffffffffu, v, 1);
            float g2 = __shfl_sync(0xffffffffu, v, 2);
            float g3 = __shfl_sync(0xffffffffu, v, 3);
            if (lane == 0) {
                float s = (v + g1) + (g2 + g3);
                float o = tanha(s + myblin);
                float r;
                if (warp == 1 || warp == 3)
                    r = exp2f(0.5f * L2E * o);
                else if (warp >= 4)
                    r = exp2f(L2E * o);
                else
                    r = o;
                s_red[warp] = r;
            }
        }
        __syncthreads();   // bar2: s_red complete

        // redundant parallel tail: every thread computes the identical update
        // (same inputs, same IEEE ops -> bitwise identical). No 3rd barrier:
        // next iter's s_acc writes are fenced by bar2, s_red writes by bar1.
        const float4 rv0 = *(const float4*)&s_red[0];
        const float4 rv4 = *(const float4*)&s_red[4];
        const float2 ep = s_eps[i];
        float inv = __frcp_rn(rv4.x + rv4.y + rv4.z);
        lm0 = rv4.x * inv;
        lm1 = rv4.y * inv;
        lx = fmaf(rv0.y, ep.x, rv0.x);   // sigx*epx + o0
        ly = fmaf(rv0.w, ep.y, rv0.z);   // sigy*epy + o2
        // warp 7 (idle in stage 2) stores the output row
        if (warp == 7 && lane < 5) {
            float sm2 = rv4.z * inv;
            float v = (lane == 0) ? lx : (lane == 1) ? ly
                    : (lane == 2) ? lm0 : (lane == 3) ? lm1 : sm2;
            out[i * 5 + lane] = v;
        }
        // argmax(row[2:]) == 2  <=>  e6 strictly beats both (uniform predicate)
        if (rv4.z > rv4.x && rv4.z > rv4.y) break;  // remaining steps: no-ops
    }
}

extern "C" void kernel_launch(void* const* d_in, const int* in_sizes, int n_in,
                              void* d_out, int out_size) {
    const float* W_ih  = (const float*)d_in[0];
    // d_in[1] = W_hh: multiplied by a provably-zero hidden state -> unused.
    const float* b_ih  = (const float*)d_in[2];
    const float* b_hh  = (const float*)d_in[3];
    const float* W_lin = (const float*)d_in[4];
    const float* b_lin = (const float*)d_in[5];
    const int*   msp   = (const int*)d_in[6];
    float* out = (float*)d_out;

    sketch_decoder_kernel<<<1, NT>>>(W_ih, b_ih, b_hh, W_lin, b_lin, msp, out);
    (void)in_sizes; (void)n_in; (void)out_size;
}

// round 16
// speedup vs baseline: 1.0356x; 1.0356x over previous
#include <cuda_runtime.h>

#define HDIM 2048
#define NT 256
#define MAXS 1000

typedef unsigned long long ull;

// ---------------- packed f32x2 helpers ----------------
__device__ __forceinline__ ull pk2(float lo, float hi) {
    ull r; asm("mov.b64 %0, {%1,%2};" : "=l"(r) : "f"(lo), "f"(hi)); return r;
}
__device__ __forceinline__ void upk2(ull v, float& lo, float& hi) {
    asm("mov.b64 {%0,%1}, %2;" : "=f"(lo), "=f"(hi) : "l"(v));
}
__device__ __forceinline__ ull fma2_(ull a, ull b, ull c) {
    ull d; asm("fma.rn.f32x2 %0, %1, %2, %3;" : "=l"(d) : "l"(a), "l"(b), "l"(c)); return d;
}
__device__ __forceinline__ ull mul2_(ull a, ull b) {
    ull d; asm("mul.rn.f32x2 %0, %1, %2;" : "=l"(d) : "l"(a), "l"(b)); return d;
}
__device__ __forceinline__ float tanha(float x) {
    float y; asm("tanh.approx.f32 %0, %1;" : "=f"(y) : "f"(x)); return y;
}

// ---------------- threefry2x32 (JAX), key = (0, 42) ----------------
__device__ __forceinline__ void threefry2x32(unsigned k1, unsigned k2,
                                             unsigned x0, unsigned x1,
                                             unsigned* o0, unsigned* o1) {
    unsigned ks0 = k1, ks1 = k2, ks2 = k1 ^ k2 ^ 0x1BD11BDAu;
    x0 += ks0; x1 += ks1;
#define TF_R(r) { x0 += x1; x1 = (x1 << (r)) | (x1 >> (32 - (r))); x1 ^= x0; }
    TF_R(13) TF_R(15) TF_R(26) TF_R(6)   x0 += ks1; x1 += ks2 + 1u;
    TF_R(17) TF_R(29) TF_R(16) TF_R(24)  x0 += ks2; x1 += ks0 + 2u;
    TF_R(13) TF_R(15) TF_R(26) TF_R(6)   x0 += ks0; x1 += ks1 + 3u;
    TF_R(17) TF_R(29) TF_R(16) TF_R(24)  x0 += ks1; x1 += ks2 + 4u;
    TF_R(13) TF_R(15) TF_R(26) TF_R(6)   x0 += ks2; x1 += ks0 + 5u;
#undef TF_R
    *o0 = x0; *o1 = x1;
}

// XLA ErfInv32 (Giles) polynomial — matches lax.erf_inv on f32.
__device__ __forceinline__ float erfinv_xla(float x) {
    float w = -logf((1.0f - x) * (1.0f + x));
    float p;
    if (w < 5.0f) {
        w -= 2.5f;
        p = 2.81022636e-08f;
        p = fmaf(p, w, 3.43273939e-07f);
        p = fmaf(p, w, -3.5233877e-06f);
        p = fmaf(p, w, -4.39150654e-06f);
        p = fmaf(p, w, 0.00021858087f);
        p = fmaf(p, w, -0.00125372503f);
        p = fmaf(p, w, -0.00417768164f);
        p = fmaf(p, w, 0.246640727f);
        p = fmaf(p, w, 1.50140941f);
    } else {
        w = sqrtf(w) - 3.0f;
        p = -0.000200214257f;
        p = fmaf(p, w, 0.000100950558f);
        p = fmaf(p, w, 0.00134934322f);
        p = fmaf(p, w, -0.00367342844f);
        p = fmaf(p, w, 0.00573950773f);
        p = fmaf(p, w, -0.0076224613f);
        p = fmaf(p, w, 0.00943887047f);
        p = fmaf(p, w, 1.00167406f);
        p = fmaf(p, w, 2.83297682f);
    }
    return p * x;
}

__device__ __forceinline__ float bits_to_normal(unsigned bits) {
    const float lo = -0.99999994f;            // nextafterf(-1, 0)
    const float span = 1.0f - lo;
    float f = __uint_as_float((bits >> 9) | 0x3f800000u) - 1.0f;  // [0,1)
    float u = fmaxf(lo, f * span + lo);
    return 1.41421356f * erfinv_xla(u);
}

__global__ void __launch_bounds__(NT, 1)
sketch_decoder_kernel(const float* __restrict__ W_ih,
                      const float* __restrict__ b_ih,
                      const float* __restrict__ b_hh,
                      const float* __restrict__ W_lin,
                      const float* __restrict__ b_lin,
                      const int*   __restrict__ msp,
                      float* __restrict__ out) {
    __shared__ float  s_acc[7][NT];      // partial sums, row-contiguous (float4 reduce)
    __shared__ float  s_red[8];          // 7 nonlinearized outputs (+pad), float4-aligned
    __shared__ float2 s_eps[MAXS];

    const int tid = threadIdx.x;
    const int warp = tid >> 5, lane = tid & 31;
    int ms = msp[0];
    if (ms < 0) ms = 0;
    if (ms > MAXS) ms = MAXS;

    // ---- init output buffer: row0 = [0,0,1,0,0], rest = [0,0,0,0,1] ----
    for (int idx = tid; idx < ms * 5; idx += NT) {
        int r = idx / 5, c = idx - r * 5;
        out[idx] = (r == 0) ? ((c == 2) ? 1.0f : 0.0f)
                            : ((c == 4) ? 1.0f : 0.0f);
    }

    // ---- precompute eps (JAX partitionable threefry, key(42)) ----
    for (int i = tid; i < ms; i += NT) {
        unsigned r0, r1;
        threefry2x32(0u, 42u, 0u, (unsigned)(2 * i), &r0, &r1);
        float ex = bits_to_normal(r0 ^ r1);
        threefry2x32(0u, 42u, 0u, (unsigned)(2 * i + 1), &r0, &r1);
        float ey = bits_to_normal(r0 ^ r1);
        s_eps[i] = make_float2(ex, ey);
    }
    if (tid == 0) s_red[7] = 0.0f;

    // per-thread bias for the reduce warps (lane 0 of warps 0-6 only)
    const float myblin = (warp < 7 && lane == 0) ? b_lin[warp] : 0.0f;

    // ---- register-resident packed weights (8 elements / thread = 4 pairs) ----
    // i,o gate rows pre-scaled by 0.5 (sigmoid via 0.5*tanh(0.5x)+0.5).
    // sum-1 fold: gate = w0*l0 + w1*l1 + (w2-w4)*sm0 + (w3-w4)*sm1 + (b + w4).
    ull wi[4][4], wg[4][4], wo[4][4], wl[4][7], bi[4], bg[4], bo[4];
    #pragma unroll
    for (int q = 0; q < 4; q++) {
        const int e0 = tid + (2 * q) * NT;
        const int e1 = e0 + NT;
        const int g0 = 2 * HDIM + e0, g1 = 2 * HDIM + e1;
        const int o0 = 3 * HDIM + e0, o1 = 3 * HDIM + e1;
        #pragma unroll
        for (int c = 0; c < 2; c++) {   // l0, l1 coefficients
            wi[q][c] = pk2(0.5f * W_ih[e0 * 5 + c], 0.5f * W_ih[e1 * 5 + c]);
            wg[q][c] = pk2(W_ih[g0 * 5 + c],        W_ih[g1 * 5 + c]);
            wo[q][c] = pk2(0.5f * W_ih[o0 * 5 + c], 0.5f * W_ih[o1 * 5 + c]);
        }
        #pragma unroll
        for (int c = 2; c < 4; c++) {   // folded sm0, sm1 coefficients
            wi[q][c] = pk2(0.5f * (W_ih[e0 * 5 + c] - W_ih[e0 * 5 + 4]),
                           0.5f * (W_ih[e1 * 5 + c] - W_ih[e1 * 5 + 4]));
            wg[q][c] = pk2(W_ih[g0 * 5 + c] - W_ih[g0 * 5 + 4],
                           W_ih[g1 * 5 + c] - W_ih[g1 * 5 + 4]);
            wo[q][c] = pk2(0.5f * (W_ih[o0 * 5 + c] - W_ih[o0 * 5 + 4]),
                           0.5f * (W_ih[o1 * 5 + c] - W_ih[o1 * 5 + 4]));
        }
        bi[q] = pk2(0.5f * (b_ih[e0] + b_hh[e0] + W_ih[e0 * 5 + 4]),
                    0.5f * (b_ih[e1] + b_hh[e1] + W_ih[e1 * 5 + 4]));
        bg[q] = pk2(b_ih[g0] + b_hh[g0] + W_ih[g0 * 5 + 4],
                    b_ih[g1] + b_hh[g1] + W_ih[g1 * 5 + 4]);
        bo[q] = pk2(0.5f * (b_ih[o0] + b_hh[o0] + W_ih[o0 * 5 + 4]),
                    0.5f * (b_ih[o1] + b_hh[o1] + W_ih[o1 * 5 + 4]));
        #pragma unroll
        for (int k = 0; k < 7; k++)
            wl[q][k] = pk2(W_lin[k * HDIM + e0], W_lin[k * HDIM + e1]);
    }

    const float L2E = 1.442695041f;
    const ull K05 = pk2(0.5f, 0.5f);
    const ull K1  = pk2(1.0f, 1.0f);
    const ull T1  = pk2(-0.33333334f, -0.33333334f);
    const ull T2  = pk2(0.13333334f, 0.13333334f);
    const ull T3  = pk2(-0.05396825f, -0.05396825f);
    const ull T4  = pk2(0.02186949f, 0.02186949f);

    // `last` lives in registers (redundant per-thread copy; identical IEEE
    // ops from identical s_red values -> identical across threads).
    float lx = 0.0f, ly = 0.0f, lm0 = 1.0f, lm1 = 0.0f;  // init row [0,0,1,0,0]

    __syncthreads();

    // step 0 of the reference is a provable no-op (write gated by i>0) -> start at 1
    for (int i = 1; i < ms; i++) {
        ull lp[4];
        lp[0] = pk2(lx, lx); lp[1] = pk2(ly, ly);
        lp[2] = pk2(lm0, lm0); lp[3] = pk2(lm1, lm1);

        ull acc[7];
        #pragma unroll
        for (int k = 0; k < 7; k++) acc[k] = 0ull;

        #pragma unroll
        for (int q = 0; q < 4; q++) {
            ull gi = bi[q], gg = bg[q], go = bo[q];
            #pragma unroll
            for (int c = 0; c < 4; c++) {
                gi = fma2_(wi[q][c], lp[c], gi);
                gg = fma2_(wg[q][c], lp[c], gg);
                go = fma2_(wo[q][c], lp[c], go);
            }
            float i0, i1, g0, g1, o0, o1;
            upk2(gi, i0, i1); upk2(gg, g0, g1); upk2(go, o0, o1);
            // sigmoid(x) = 0.5*tanh(0.5x)+0.5 ; 0.5 pre-folded into gi/go.
            // Packed post-gate algebra (issue-count cut):
            ull sip = fma2_(pk2(tanha(i0), tanha(i1)), K05, K05);
            ull sop = fma2_(pk2(tanha(o0), tanha(o1)), K05, K05);
            ull cp  = mul2_(sip, pk2(tanha(g0), tanha(g1)));
            ull tcp;
            if (q < 1) {
                // Taylor-9 tanh, packed (1 of 4 blocks; pipe rebalance)
                ull t = mul2_(cp, cp);
                ull p = fma2_(T4, t, T3);
                p = fma2_(p, t, T2);
                p = fma2_(p, t, T1);
                p = fma2_(p, t, K1);
                tcp = mul2_(p, cp);
            } else {
                float c0, c1; upk2(cp, c0, c1);
                tcp = pk2(tanha(c0), tanha(c1));
            }
            ull hp = mul2_(sop, tcp);
            #pragma unroll
            for (int k = 0; k < 7; k++)
                acc[k] = fma2_(wl[q][k], hp, acc[k]);
        }

        #pragma unroll
        for (int k = 0; k < 7; k++) {
            float a0, a1; upk2(acc[k], a0, a1);
            s_acc[k][tid] = a0 + a1;
        }
        __syncthreads();   // bar1: s_acc complete

        // warps 0-6: reduce output k=warp over 256 partials, then nonlinearity:
        //   k=0,2 : tanh(o_k)            (raw, for sx/sy)
        //   k=1,3 : exp(0.5*tanh(o_k))   (sig_x / sig_y)
        //   k=4..6: exp(tanh(o_k))       (unnormalized softmax; arg in [-1,1])
        if (warp < 7) {
            const float4* row = (const float4*)s_acc[warp];
            float4 v0 = row[lane];
            float4 v1 = row[lane + 32];
            float v = ((v0.x + v0.y) + (v0.z + v0.w))
                    + ((v1.x + v1.y) + (v1.z + v1.w));
            // 2 xor rounds -> lane l holds sum over {l, l+8, l+16, l+24}
            v += __shfl_xor_sync(0xffffffffu, v, 16);
            v += __shfl_xor_sync(0xffffffffu, v, 8);
            // parallel gather of the 7 remaining mod-8 classes + 3-deep tree
            float g1 = __shfl_sync(0xffffffffu, v, 1);
            float g2 = __shfl_sync(0xffffffffu, v, 2);
            float g3 = __shfl_sync(0xffffffffu, v, 3);
            float g4 = __shfl_sync(0xffffffffu, v, 4);
            float g5 = __shfl_sync(0xffffffffu, v, 5);
            float g6 = __shfl_sync(0xffffffffu, v, 6);
            float g7 = __shfl_sync(0xffffffffu, v, 7);
            if (lane == 0) {
                float s = (((v + g1) + (g2 + g3)) + ((g4 + g5) + (g6 + g7)));
                float o = tanha(s + myblin);
                float r;
                if (warp == 1 || warp == 3)
                    r = exp2f(0.5f * L2E * o);
                else if (warp >= 4)
                    r = exp2f(L2E * o);
                else
                    r = o;
                s_red[warp] = r;
            }
        }
        __syncthreads();   // bar2: s_red complete

        // redundant parallel tail: every thread computes the identical update
        // (same inputs, same IEEE ops -> bitwise identical). No 3rd barrier:
        // next iter's s_acc writes are fenced by bar2, s_red writes by bar1.
        const float4 rv0 = *(const float4*)&s_red[0];
        const float4 rv4 = *(const float4*)&s_red[4];
        const float2 ep = s_eps[i];
        float inv = __frcp_rn(rv4.x + rv4.y + rv4.z);
        lm0 = rv4.x * inv;
        lm1 = rv4.y * inv;
        lx = fmaf(rv0.y, ep.x, rv0.x);   // sigx*epx + o0
        ly = fmaf(rv0.w, ep.y, rv0.z);   // sigy*epy + o2
        // warp 7 (idle in stage 2) stores the output row
        if (warp == 7 && lane < 5) {
            float sm2 = rv4.z * inv;
            float v = (lane == 0) ? lx : (lane == 1) ? ly
                    : (lane == 2) ? lm0 : (lane == 3) ? lm1 : sm2;
            out[i * 5 + lane] = v;
        }
        // argmax(row[2:]) == 2  <=>  e6 strictly beats both (uniform predicate)
        if (rv4.z > rv4.x && rv4.z > rv4.y) break;  // remaining steps: no-ops
    }
}

extern "C" void kernel_launch(void* const* d_in, const int* in_sizes, int n_in,
                              void* d_out, int out_size) {
    const float* W_ih  = (const float*)d_in[0];
    // d_in[1] = W_hh: multiplied by a provably-zero hidden state -> unused.
    const float* b_ih  = (const float*)d_in[2];
    const float* b_hh  = (const float*)d_in[3];
    const float* W_lin = (const float*)d_in[4];
    const float* b_lin = (const float*)d_in[5];
    const int*   msp   = (const int*)d_in[6];
    float* out = (float*)d_out;

    sketch_decoder_kernel<<<1, NT>>>(W_ih, b_ih, b_hh, W_lin, b_lin, msp, out);
    (void)in_sizes; (void)n_in; (void)out_size;
}

// round 17
// speedup vs baseline: 1.0522x; 1.0160x over previous
#include <cuda_runtime.h>

#define HDIM 2048
#define NT 256
#define MAXS 1000

typedef unsigned long long ull;

// ---------------- packed f32x2 helpers ----------------
__device__ __forceinline__ ull pk2(float lo, float hi) {
    ull r; asm("mov.b64 %0, {%1,%2};" : "=l"(r) : "f"(lo), "f"(hi)); return r;
}
__device__ __forceinline__ void upk2(ull v, float& lo, float& hi) {
    asm("mov.b64 {%0,%1}, %2;" : "=f"(lo), "=f"(hi) : "l"(v));
}
__device__ __forceinline__ ull fma2_(ull a, ull b, ull c) {
    ull d; asm("fma.rn.f32x2 %0, %1, %2, %3;" : "=l"(d) : "l"(a), "l"(b), "l"(c)); return d;
}
__device__ __forceinline__ ull mul2_(ull a, ull b) {
    ull d; asm("mul.rn.f32x2 %0, %1, %2;" : "=l"(d) : "l"(a), "l"(b)); return d;
}
__device__ __forceinline__ float tanha(float x) {
    float y; asm("tanh.approx.f32 %0, %1;" : "=f"(y) : "f"(x)); return y;
}

// ---------------- threefry2x32 (JAX), key = (0, 42) ----------------
__device__ __forceinline__ void threefry2x32(unsigned k1, unsigned k2,
                                             unsigned x0, unsigned x1,
                                             unsigned* o0, unsigned* o1) {
    unsigned ks0 = k1, ks1 = k2, ks2 = k1 ^ k2 ^ 0x1BD11BDAu;
    x0 += ks0; x1 += ks1;
#define TF_R(r) { x0 += x1; x1 = (x1 << (r)) | (x1 >> (32 - (r))); x1 ^= x0; }
    TF_R(13) TF_R(15) TF_R(26) TF_R(6)   x0 += ks1; x1 += ks2 + 1u;
    TF_R(17) TF_R(29) TF_R(16) TF_R(24)  x0 += ks2; x1 += ks0 + 2u;
    TF_R(13) TF_R(15) TF_R(26) TF_R(6)   x0 += ks0; x1 += ks1 + 3u;
    TF_R(17) TF_R(29) TF_R(16) TF_R(24)  x0 += ks1; x1 += ks2 + 4u;
    TF_R(13) TF_R(15) TF_R(26) TF_R(6)   x0 += ks2; x1 += ks0 + 5u;
#undef TF_R
    *o0 = x0; *o1 = x1;
}

// XLA ErfInv32 (Giles) polynomial — matches lax.erf_inv on f32.
__device__ __forceinline__ float erfinv_xla(float x) {
    float w = -logf((1.0f - x) * (1.0f + x));
    float p;
    if (w < 5.0f) {
        w -= 2.5f;
        p = 2.81022636e-08f;
        p = fmaf(p, w, 3.43273939e-07f);
        p = fmaf(p, w, -3.5233877e-06f);
        p = fmaf(p, w, -4.39150654e-06f);
        p = fmaf(p, w, 0.00021858087f);
        p = fmaf(p, w, -0.00125372503f);
        p = fmaf(p, w, -0.00417768164f);
        p = fmaf(p, w, 0.246640727f);
        p = fmaf(p, w, 1.50140941f);
    } else {
        w = sqrtf(w) - 3.0f;
        p = -0.000200214257f;
        p = fmaf(p, w, 0.000100950558f);
        p = fmaf(p, w, 0.00134934322f);
        p = fmaf(p, w, -0.00367342844f);
        p = fmaf(p, w, 0.00573950773f);
        p = fmaf(p, w, -0.0076224613f);
        p = fmaf(p, w, 0.00943887047f);
        p = fmaf(p, w, 1.00167406f);
        p = fmaf(p, w, 2.83297682f);
    }
    return p * x;
}

__device__ __forceinline__ float bits_to_normal(unsigned bits) {
    const float lo = -0.99999994f;            // nextafterf(-1, 0)
    const float span = 1.0f - lo;
    float f = __uint_as_float((bits >> 9) | 0x3f800000u) - 1.0f;  // [0,1)
    float u = fmaxf(lo, f * span + lo);
    return 1.41421356f * erfinv_xla(u);
}

__global__ void __launch_bounds__(NT, 1)
sketch_decoder_kernel(const float* __restrict__ W_ih,
                      const float* __restrict__ b_ih,
                      const float* __restrict__ b_hh,
                      const float* __restrict__ W_lin,
                      const float* __restrict__ b_lin,
                      const int*   __restrict__ msp,
                      float* __restrict__ out) {
    __shared__ float  s_acc[7][NT];      // partial sums, row-contiguous (float4 reduce)
    __shared__ float  s_red[8];          // 7 nonlinearized outputs (+pad), float4-aligned
    __shared__ float2 s_eps[MAXS];

    const int tid = threadIdx.x;
    const int warp = tid >> 5, lane = tid & 31;
    int ms = msp[0];
    if (ms < 0) ms = 0;
    if (ms > MAXS) ms = MAXS;

    // ---- init output buffer: row0 = [0,0,1,0,0], rest = [0,0,0,0,1] ----
    for (int idx = tid; idx < ms * 5; idx += NT) {
        int r = idx / 5, c = idx - r * 5;
        out[idx] = (r == 0) ? ((c == 2) ? 1.0f : 0.0f)
                            : ((c == 4) ? 1.0f : 0.0f);
    }

    // ---- precompute eps (JAX partitionable threefry, key(42)) ----
    for (int i = tid; i < ms; i += NT) {
        unsigned r0, r1;
        threefry2x32(0u, 42u, 0u, (unsigned)(2 * i), &r0, &r1);
        float ex = bits_to_normal(r0 ^ r1);
        threefry2x32(0u, 42u, 0u, (unsigned)(2 * i + 1), &r0, &r1);
        float ey = bits_to_normal(r0 ^ r1);
        s_eps[i] = make_float2(ex, ey);
    }
    if (tid == 0) s_red[7] = 0.0f;

    // per-thread bias for the reduce warps (lane 0 of warps 0-6 only)
    const float myblin = (warp < 7 && lane == 0) ? b_lin[warp] : 0.0f;

    // ---- register-resident packed weights (8 elements / thread = 4 pairs) ----
    // i,o gate rows pre-scaled by 0.5 (sigmoid via 0.5*tanh(0.5x)+0.5).
    // sum-1 fold: gate = w0*l0 + w1*l1 + (w2-w4)*sm0 + (w3-w4)*sm1 + (b + w4).
    ull wi[4][4], wg[4][4], wo[4][4], wl[4][7], bi[4], bg[4], bo[4];
    #pragma unroll
    for (int q = 0; q < 4; q++) {
        const int e0 = tid + (2 * q) * NT;
        const int e1 = e0 + NT;
        const int g0 = 2 * HDIM + e0, g1 = 2 * HDIM + e1;
        const int o0 = 3 * HDIM + e0, o1 = 3 * HDIM + e1;
        #pragma unroll
        for (int c = 0; c < 2; c++) {   // l0, l1 coefficients
            wi[q][c] = pk2(0.5f * W_ih[e0 * 5 + c], 0.5f * W_ih[e1 * 5 + c]);
            wg[q][c] = pk2(W_ih[g0 * 5 + c],        W_ih[g1 * 5 + c]);
            wo[q][c] = pk2(0.5f * W_ih[o0 * 5 + c], 0.5f * W_ih[o1 * 5 + c]);
        }
        #pragma unroll
        for (int c = 2; c < 4; c++) {   // folded sm0, sm1 coefficients
            wi[q][c] = pk2(0.5f * (W_ih[e0 * 5 + c] - W_ih[e0 * 5 + 4]),
                           0.5f * (W_ih[e1 * 5 + c] - W_ih[e1 * 5 + 4]));
            wg[q][c] = pk2(W_ih[g0 * 5 + c] - W_ih[g0 * 5 + 4],
                           W_ih[g1 * 5 + c] - W_ih[g1 * 5 + 4]);
            wo[q][c] = pk2(0.5f * (W_ih[o0 * 5 + c] - W_ih[o0 * 5 + 4]),
                           0.5f * (W_ih[o1 * 5 + c] - W_ih[o1 * 5 + 4]));
        }
        bi[q] = pk2(0.5f * (b_ih[e0] + b_hh[e0] + W_ih[e0 * 5 + 4]),
                    0.5f * (b_ih[e1] + b_hh[e1] + W_ih[e1 * 5 + 4]));
        bg[q] = pk2(b_ih[g0] + b_hh[g0] + W_ih[g0 * 5 + 4],
                    b_ih[g1] + b_hh[g1] + W_ih[g1 * 5 + 4]);
        bo[q] = pk2(0.5f * (b_ih[o0] + b_hh[o0] + W_ih[o0 * 5 + 4]),
                    0.5f * (b_ih[o1] + b_hh[o1] + W_ih[o1 * 5 + 4]));
        #pragma unroll
        for (int k = 0; k < 7; k++)
            wl[q][k] = pk2(W_lin[k * HDIM + e0], W_lin[k * HDIM + e1]);
    }

    const float L2E = 1.442695041f;
    const ull K05 = pk2(0.5f, 0.5f);
    const ull K1  = pk2(1.0f, 1.0f);
    const ull T1  = pk2(-0.33333334f, -0.33333334f);
    const ull T2  = pk2(0.13333334f, 0.13333334f);
    const ull T3  = pk2(-0.05396825f, -0.05396825f);
    const ull T4  = pk2(0.02186949f, 0.02186949f);

    // `last` lives in registers (redundant per-thread copy; identical IEEE
    // ops from identical s_red values -> identical across threads).
    float lx = 0.0f, ly = 0.0f, lm0 = 1.0f, lm1 = 0.0f;  // init row [0,0,1,0,0]

    __syncthreads();

    // step 0 of the reference is a provable no-op (write gated by i>0) -> start at 1
    for (int i = 1; i < ms; i++) {
        ull lp[4];
        lp[0] = pk2(lx, lx); lp[1] = pk2(ly, ly);
        lp[2] = pk2(lm0, lm0); lp[3] = pk2(lm1, lm1);

        ull acc[7];
        #pragma unroll
        for (int k = 0; k < 7; k++) acc[k] = 0ull;

        #pragma unroll
        for (int q = 0; q < 4; q++) {
            ull gi = bi[q], gg = bg[q], go = bo[q];
            #pragma unroll
            for (int c = 0; c < 4; c++) {
                gi = fma2_(wi[q][c], lp[c], gi);
                gg = fma2_(wg[q][c], lp[c], gg);
                go = fma2_(wo[q][c], lp[c], go);
            }
            float i0, i1, g0, g1, o0, o1;
            upk2(gi, i0, i1); upk2(gg, g0, g1); upk2(go, o0, o1);
            // sigmoid(x) = 0.5*tanh(0.5x)+0.5 ; 0.5 pre-folded into gi/go.
            ull sip = fma2_(pk2(tanha(i0), tanha(i1)), K05, K05);
            ull sop = fma2_(pk2(tanha(o0), tanha(o1)), K05, K05);
            ull cp  = mul2_(sip, pk2(tanha(g0), tanha(g1)));
            // Taylor-9 tanh on ALL c pairs (MUFU 30->24 instr/thread; MUFU
            // is the binding pipe at 480 cyc/SMSP -> 384). |c| small;
            // 3/4 pairs validated at ~3e-7 across R4/R8/R13, 4th identical stats.
            ull t = mul2_(cp, cp);
            ull p = fma2_(T4, t, T3);
            p = fma2_(p, t, T2);
            p = fma2_(p, t, T1);
            p = fma2_(p, t, K1);
            ull tcp = mul2_(p, cp);
            ull hp = mul2_(sop, tcp);
            #pragma unroll
            for (int k = 0; k < 7; k++)
                acc[k] = fma2_(wl[q][k], hp, acc[k]);
        }

        #pragma unroll
        for (int k = 0; k < 7; k++) {
            float a0, a1; upk2(acc[k], a0, a1);
            s_acc[k][tid] = a0 + a1;
        }
        __syncthreads();   // bar1: s_acc complete

        // warps 0-6: reduce output k=warp over 256 partials, then nonlinearity:
        //   k=0,2 : tanh(o_k)            (raw, for sx/sy)
        //   k=1,3 : exp(0.5*tanh(o_k))   (sig_x / sig_y)
        //   k=4..6: exp(tanh(o_k))       (unnormalized softmax; arg in [-1,1])
        if (warp < 7) {
            const float4* row = (const float4*)s_acc[warp];
            float4 v0 = row[lane];
            float4 v1 = row[lane + 32];
            float v = ((v0.x + v0.y) + (v0.z + v0.w))
                    + ((v1.x + v1.y) + (v1.z + v1.w));
            // 2 xor rounds -> lane l holds sum over {l, l+8, l+16, l+24}
            v += __shfl_xor_sync(0xffffffffu, v, 16);
            v += __shfl_xor_sync(0xffffffffu, v, 8);
            // parallel gather of the 7 remaining mod-8 classes + 3-deep tree
            float g1 = __shfl_sync(0xffffffffu, v, 1);
            float g2 = __shfl_sync(0xffffffffu, v, 2);
            float g3 = __shfl_sync(0xffffffffu, v, 3);
            float g4 = __shfl_sync(0xffffffffu, v, 4);
            float g5 = __shfl_sync(0xffffffffu, v, 5);
            float g6 = __shfl_sync(0xffffffffu, v, 6);
            float g7 = __shfl_sync(0xffffffffu, v, 7);
            if (lane == 0) {
                float s = (((v + g1) + (g2 + g3)) + ((g4 + g5) + (g6 + g7)));
                float o = tanha(s + myblin);
                float r;
                if (warp == 1 || warp == 3)
                    r = exp2f(0.5f * L2E * o);
                else if (warp >= 4)
                    r = exp2f(L2E * o);
                else
                    r = o;
                s_red[warp] = r;
            }
        }
        __syncthreads();   // bar2: s_red complete

        // redundant parallel tail: every thread computes the identical update
        // (same inputs, same IEEE ops -> bitwise identical). No 3rd barrier:
        // next iter's s_acc writes are fenced by bar2, s_red writes by bar1.
        const float4 rv0 = *(const float4*)&s_red[0];
        const float4 rv4 = *(const float4*)&s_red[4];
        const float2 ep = s_eps[i];
        float inv = __frcp_rn(rv4.x + rv4.y + rv4.z);
        lm0 = rv4.x * inv;
        lm1 = rv4.y * inv;
        lx = fmaf(rv0.y, ep.x, rv0.x);   // sigx*epx + o0
        ly = fmaf(rv0.w, ep.y, rv0.z);   // sigy*epy + o2
        // warp 7 (idle in stage 2) stores the output row
        if (warp == 7 && lane < 5) {
            float sm2 = rv4.z * inv;
            float v = (lane == 0) ? lx : (lane == 1) ? ly
                    : (lane == 2) ? lm0 : (lane == 3) ? lm1 : sm2;
            out[i * 5 + lane] = v;
        }
        // argmax(row[2:]) == 2  <=>  e6 strictly beats both (uniform predicate)
        if (rv4.z > rv4.x && rv4.z > rv4.y) break;  // remaining steps: no-ops
    }
}

extern "C" void kernel_launch(void* const* d_in, const int* in_sizes, int n_in,
                              void* d_out, int out_size) {
    const float* W_ih  = (const float*)d_in[0];
    // d_in[1] = W_hh: multiplied by a provably-zero hidden state -> unused.
    const float* b_ih  = (const float*)d_in[2];
    const float* b_hh  = (const float*)d_in[3];
    const float* W_lin = (const float*)d_in[4];
    const float* b_lin = (const float*)d_in[5];
    const int*   msp   = (const int*)d_in[6];
    float* out = (float*)d_out;

    sketch_decoder_kernel<<<1, NT>>>(W_ih, b_ih, b_hh, W_lin, b_lin, msp, out);
    (void)in_sizes; (void)n_in; (void)out_size;
}